// round 1
// baseline (speedup 1.0000x reference)
#include <cuda_runtime.h>
#include <cuda_bf16.h>
#include <cstddef>

// Problem sizes (fixed by the reference)
constexpr int NN = 4096;   // nodes
constexpr int DD = 512;    // feature dim (in == out)

// Tiling
constexpr int BM = 128;
constexpr int BN = 64;
constexpr int BK = 16;
constexpr int LDA_S = 136; // padded (multiple of 4 floats -> 16B aligned rows, breaks bank patterns)
constexpr int LDB_S = 68;  // padded (multiple of 4 floats)

// Scratch (device globals: allocation-free)
__device__ float g_Y[(size_t)NN * DD];   // A2 @ X
__device__ float g_Ts[(size_t)NN * DD];  // ds .* (Y @ W^T)
__device__ float g_ds[NN];               // (A[i,i]+1)^(-1/2)

__global__ void dscale_kernel(const float* __restrict__ A) {
    int i = blockIdx.x * blockDim.x + threadIdx.x;
    if (i < NN) {
        g_ds[i] = rsqrtf(A[(size_t)i * NN + i] + 1.0f);
    }
}

// MODE 0: O(=g_Y)  = Aext @ Bext + Bext[i,:]        (Aext=A, Bext=X, K=4096)
// MODE 1: O(=g_Ts) = ds[i] * (g_Y @ Bext^T)         (Bext=W [out,in], K=512)
// MODE 2: O(=out)  = relu(ds[i]*(Aext @ g_Ts + g_Ts[i,:]))   (Aext=A, K=4096)
template <int MODE>
__global__ void __launch_bounds__(256, 4)
gemm_k(const float* __restrict__ Aext,
       const float* __restrict__ Bext,
       float* __restrict__ Oext)
{
    constexpr int K   = (MODE == 1) ? DD : NN;
    constexpr int LDA = (MODE == 1) ? DD : NN;

    __shared__ float As[BK][LDA_S];
    __shared__ float Bs[BK][LDB_S];

    const float* Ag = (MODE == 1) ? g_Y  : Aext;
    const float* Bg = (MODE == 2) ? g_Ts : Bext;
    float*       Og = (MODE == 0) ? g_Y  : (MODE == 1) ? g_Ts : Oext;

    const int tid = threadIdx.x;
    const int tx  = tid & 15;   // 0..15  -> 4 output cols each
    const int ty  = tid >> 4;   // 0..15  -> 8 output rows each
    const int m0  = blockIdx.y * BM;
    const int n0  = blockIdx.x * BN;

    float acc[8][4];
    #pragma unroll
    for (int i = 0; i < 8; i++)
        #pragma unroll
        for (int j = 0; j < 4; j++) acc[i][j] = 0.0f;

    // A-tile load mapping: 512 float4 loads, 2 per thread
    const int arow = tid >> 2;        // 0..63 (second pass +64)
    const int akq  = (tid & 3) * 4;   // k offset within BK

    for (int k0 = 0; k0 < K; k0 += BK) {
        // ---- load A tile (transposed into smem: As[k][m]) ----
        #pragma unroll
        for (int p = 0; p < 2; p++) {
            const int r = arow + p * 64;
            float4 v = *(const float4*)&Ag[(size_t)(m0 + r) * LDA + k0 + akq];
            As[akq + 0][r] = v.x;
            As[akq + 1][r] = v.y;
            As[akq + 2][r] = v.z;
            As[akq + 3][r] = v.w;
        }
        // ---- load B tile ----
        if (MODE == 1) {
            // B = W^T : Bs[k][n] = W[(n0+n)*DD + k0+k]
            const int n  = tid >> 2;         // 0..63
            const int kq = (tid & 3) * 4;
            float4 v = *(const float4*)&Bg[(size_t)(n0 + n) * DD + k0 + kq];
            Bs[kq + 0][n] = v.x;
            Bs[kq + 1][n] = v.y;
            Bs[kq + 2][n] = v.z;
            Bs[kq + 3][n] = v.w;
        } else {
            // B row-major [K, DD]
            const int kk = tid >> 4;          // 0..15
            const int n4 = (tid & 15) * 4;
            float4 v = *(const float4*)&Bg[(size_t)(k0 + kk) * DD + n0 + n4];
            *(float4*)&Bs[kk][n4] = v;
        }
        __syncthreads();

        // ---- compute ----
        #pragma unroll
        for (int k = 0; k < BK; k++) {
            float4 a0 = *(const float4*)&As[k][ty * 8];
            float4 a1 = *(const float4*)&As[k][ty * 8 + 4];
            float4 b  = *(const float4*)&Bs[k][tx * 4];
            float av[8] = {a0.x, a0.y, a0.z, a0.w, a1.x, a1.y, a1.z, a1.w};
            float bv[4] = {b.x, b.y, b.z, b.w};
            #pragma unroll
            for (int i = 0; i < 8; i++)
                #pragma unroll
                for (int j = 0; j < 4; j++)
                    acc[i][j] = fmaf(av[i], bv[j], acc[i][j]);
        }
        __syncthreads();
    }

    // ---- epilogue ----
    #pragma unroll
    for (int i = 0; i < 8; i++) {
        const int row = m0 + ty * 8 + i;
        const float ds = (MODE != 0) ? g_ds[row] : 0.0f;
        #pragma unroll
        for (int j = 0; j < 4; j++) {
            const int col = n0 + tx * 4 + j;
            float v = acc[i][j];
            if (MODE == 0) {
                // + I @ X  (Bg here IS X)
                v += Bg[(size_t)row * DD + col];
            } else if (MODE == 1) {
                v *= ds;
            } else { // MODE == 2
                // + Ts[row,:] (identity term), scale, relu.  Bg here IS g_Ts.
                v = ds * (v + Bg[(size_t)row * DD + col]);
                v = fmaxf(v, 0.0f);
            }
            Og[(size_t)row * DD + col] = v;
        }
    }
}

extern "C" void kernel_launch(void* const* d_in, const int* in_sizes, int n_in,
                              void* d_out, int out_size)
{
    const float* X = (const float*)d_in[0];  // [4096, 512]
    const float* A = (const float*)d_in[1];  // [4096, 4096]
    const float* W = (const float*)d_in[2];  // [512, 512] (out, in)
    float* out = (float*)d_out;              // [4096, 512]

    // 1) diagonal scale
    dscale_kernel<<<(NN + 255) / 256, 256>>>(A);

    dim3 grid(DD / BN, NN / BM);  // (8, 32)
    dim3 block(256);

    // 2) Y = A@X + X
    gemm_k<0><<<grid, block>>>(A, X, nullptr);
    // 3) Ts = ds .* (Y @ W^T)
    gemm_k<1><<<grid, block>>>(nullptr, W, nullptr);
    // 4) out = relu(ds .* (A@Ts + Ts))
    gemm_k<2><<<grid, block>>>(A, nullptr, out);
}